// round 13
// baseline (speedup 1.0000x reference)
#include <cuda_runtime.h>

#define B_DIM 128
#define N_DIM 8192
#define HW    49

typedef unsigned long long u64;
typedef unsigned int u32;

__device__ __forceinline__ u64 pk2(float lo, float hi) {
    u64 r; asm("mov.b64 %0, {%1,%2};" : "=l"(r) : "f"(lo), "f"(hi)); return r;
}
__device__ __forceinline__ void upk2(u64 v, float& lo, float& hi) {
    asm("mov.b64 {%0,%1}, %2;" : "=f"(lo), "=f"(hi) : "l"(v));
}
__device__ __forceinline__ u64 fma2(u64 a, u64 b, u64 c) {
    u64 d; asm("fma.rn.f32x2 %0, %1, %2, %3;" : "=l"(d) : "l"(a), "l"(b), "l"(c)); return d;
}
__device__ __forceinline__ u64 add2(u64 a, u64 b) {
    u64 d; asm("add.rn.f32x2 %0, %1, %2;" : "=l"(d) : "l"(a), "l"(b)); return d;
}
__device__ __forceinline__ float ex2f(float x) {
    float y; asm("ex2.approx.ftz.f32 %0, %1;" : "=f"(y) : "f"(x)); return y;
}
// two scalar f32 scores -> one f16x2 -> one MUFU for two exps
__device__ __forceinline__ u32 ex2h2s(float slo, float shi) {
    u32 h; asm("cvt.rn.f16x2.f32 %0, %1, %2;" : "=r"(h) : "f"(shi), "f"(slo));
    u32 e; asm("ex2.approx.f16x2 %0, %1;" : "=r"(e) : "r"(h));
    return e;
}

__global__ __launch_bounds__(128, 12) void rsca_kernel(
    const float* __restrict__ x, const float* __restrict__ y,
    const float* __restrict__ swq, const float* __restrict__ swk,
    const float* __restrict__ swv, const float* __restrict__ sbq,
    const float* __restrict__ sbk, const float* __restrict__ sbv,
    const float* __restrict__ swo, const float* __restrict__ sbo,
    float* __restrict__ out)
{
    const int n = blockIdx.x;
    const int i = threadIdx.x;

    __shared__ float4 kv[B_DIM];    // {kx, ky, vx, vy}  (2 KB)
    __shared__ float4 wred[4];

    const float wq = *swq, wk = *swk, wv = *swv;
    const float bq = *sbq, bk = *sbk, bv = *sbv;
    const float wo = *swo, bo = *sbo;

    // ---- Pooling: DIRECT per-thread aligned float4 loads (R2 style, 2KB smem) ----
    // Element offset s = (i*8192+n)*49; s mod 4 == n mod 4 == a (uniform per block).
    // base = &x[s-a] is 16B-aligned. Window w[p]=base[p]; valid row = p in [a, a+48].
    const int a = n & 3;
    const float* base = x + ((size_t)i * N_DIM + (size_t)n) * HW - a;
    const float4* b4 = (const float4*)base;

    float4 a0 = b4[0], a1 = b4[1], a2 = b4[2],  a3 = b4[3];
    float4 a4 = b4[4], a5 = b4[5], a6 = b4[6],  a7 = b4[7];
    float4 a8 = b4[8], a9 = b4[9], a10 = b4[10], a11 = b4[11];
    float4 a12 = b4[12];

    float4 t0, t1, t2;
    t0.x = a0.x + a1.x; t0.y = a0.y + a1.y; t0.z = a0.z + a1.z; t0.w = a0.w + a1.w;
    t1.x = a2.x + a3.x; t1.y = a2.y + a3.y; t1.z = a2.z + a3.z; t1.w = a2.w + a3.w;
    t2.x = a4.x + a5.x; t2.y = a4.y + a5.y; t2.z = a4.z + a5.z; t2.w = a4.w + a5.w;
    t0.x += a6.x;  t0.y += a6.y;  t0.z += a6.z;  t0.w += a6.w;
    t1.x += a7.x;  t1.y += a7.y;  t1.z += a7.z;  t1.w += a7.w;
    t2.x += a8.x;  t2.y += a8.y;  t2.z += a8.z;  t2.w += a8.w;
    t0.x += a9.x;  t0.y += a9.y;  t0.z += a9.z;  t0.w += a9.w;
    t1.x += a10.x; t1.y += a10.y; t1.z += a10.z; t1.w += a10.w;
    t2.x += a11.x; t2.y += a11.y; t2.z += a11.z; t2.w += a11.w;
    t0.x += a12.x; t0.y += a12.y; t0.z += a12.z; t0.w += a12.w;

    float sum = (t0.x + t0.y) + (t0.z + t0.w)
              + (t1.x + t1.y) + (t1.z + t1.w)
              + (t2.x + t2.y) + (t2.z + t2.w);   // w0..w51 each exactly once

    // valid window = [a, a+48]; remove the 3 invalid of the 52 loaded
    if (a >= 1) sum -= a0.x;   else sum -= a12.y;   // w0  vs w49
    if (a >= 2) sum -= a0.y;   else sum -= a12.z;   // w1  vs w50
    if (a >= 3) sum -= a0.z;   else sum -= a12.w;   // w2  vs w51

    const float ax = sum * (1.0f / 49.0f);
    const float ay = y[(size_t)i * N_DIM + (size_t)n];

    // ---- projections (k pre-scaled by log2 e) ----
    const float L2E = 1.4426950408889634f;
    const float qx = fmaf(ax, wq, bq);
    const float qy = fmaf(ay, wq, bq);
    const float kx = fmaf(ax, wk, bk) * L2E;
    const float ky = fmaf(ay, wk, bk) * L2E;
    const float vx = fmaf(ax, wv, bv);
    const float vy = fmaf(ay, wv, bv);

    kv[i] = make_float4(kx, ky, vx, vy);

    // ---- block min/max of kx, ky (analytic per-row softmax max) ----
    float kxmx = kx, kxmn = kx, kymx = ky, kymn = ky;
    #pragma unroll
    for (int off = 16; off; off >>= 1) {
        kxmx = fmaxf(kxmx, __shfl_xor_sync(0xFFFFFFFFu, kxmx, off));
        kxmn = fminf(kxmn, __shfl_xor_sync(0xFFFFFFFFu, kxmn, off));
        kymx = fmaxf(kymx, __shfl_xor_sync(0xFFFFFFFFu, kymx, off));
        kymn = fminf(kymn, __shfl_xor_sync(0xFFFFFFFFu, kymn, off));
    }
    if ((i & 31) == 0) wred[i >> 5] = make_float4(kxmx, kxmn, kymx, kymn);
    __syncthreads();
    {
        float4 r0 = wred[0], r1 = wred[1], r2 = wred[2], r3 = wred[3];
        kxmx = fmaxf(fmaxf(r0.x, r1.x), fmaxf(r2.x, r3.x));
        kxmn = fminf(fminf(r0.y, r1.y), fminf(r2.y, r3.y));
        kymx = fmaxf(fmaxf(r0.z, r1.z), fmaxf(r2.z, r3.z));
        kymn = fminf(fminf(r0.w, r1.w), fminf(r2.w, r3.w));
    }

    const float nm1 = -((qx >= 0.f) ? qx * kxmx : qx * kxmn);  // self_x : qx,kx
    const float nm2 = -((qy >= 0.f) ? qy * kymx : qy * kymn);  // self_y : qy,ky
    const float nm3 = -((qx >= 0.f) ? qx * kymx : qx * kymn);  // cross_x: qx,ky
    const float nm4 = -((qy >= 0.f) ? qy * kxmx : qy * kxmn);  // cross_y: qy,kx

    // ---- fused 4-combo attention, scalar idiom, 3 MUFU/j ----
    // combos 1,2: exact scalar f32 MUFU. combos 4,3: one f16x2 MUFU.
    float d1 = 0.f, n1 = 0.f, d2 = 0.f, n2 = 0.f;
    u64 d43 = 0, n43 = 0;                 // packed {c4, c3} accumulators

    #pragma unroll 8
    for (int j = 0; j < B_DIM; ++j) {
        const float4 p = kv[j];           // {kx, ky, vx, vy} via broadcast LDS.128

        const float s1 = fmaf(qx, p.x, nm1);
        const float s2 = fmaf(qy, p.y, nm2);
        const float s4 = fmaf(qy, p.x, nm4);
        const float s3 = fmaf(qx, p.y, nm3);

        const float e1 = ex2f(s1);
        const float e2 = ex2f(s2);
        const u32 eh = ex2h2s(s4, s3);    // f16x2 {2^s4, 2^s3}

        // exact unpack, scaled 2^-112 (cancels in n/d); masks load-bearing
        const u32 lo = (eh << 13) & 0x0FFFE000u;
        const u32 hi = (eh >> 3)  & 0x0FFFE000u;
        const u64 f43 = pk2(__uint_as_float(lo), __uint_as_float(hi));

        d1 += e1; n1 = fmaf(e1, p.z, n1);
        d2 += e2; n2 = fmaf(e2, p.w, n2);
        const u64 vp = pk2(p.z, p.w);     // aligned pair from LDS.128: no MOV
        d43 = add2(d43, f43);
        n43 = fma2(f43, vp, n43);          // n4+=e4*vx, n3+=e3*vy
    }

    float nn4, nn3, dd4, dd3;
    upk2(n43, nn4, nn3); upk2(d43, dd4, dd3);

    const float osx = __fdividef(n1, d1);
    const float osy = __fdividef(n2, d2);
    const float ocx = __fdividef(nn3, dd3);   // 2^-112 scale cancels
    const float ocy = __fdividef(nn4, dd4);

    const float ox = fmaf(wo, osx + ocx, ax + 2.0f * bo);
    const float oy = fmaf(wo, osy + ocy, ay + 2.0f * bo);

    out[(size_t)i * (2 * N_DIM) + (size_t)n]         = ox;
    out[(size_t)i * (2 * N_DIM) + N_DIM + (size_t)n] = oy;
}

extern "C" void kernel_launch(void* const* d_in, const int* in_sizes, int n_in,
                              void* d_out, int out_size) {
    const float* x   = (const float*)d_in[0];
    const float* y   = (const float*)d_in[1];
    const float* swq = (const float*)d_in[2];
    const float* swk = (const float*)d_in[3];
    const float* swv = (const float*)d_in[4];
    const float* sbq = (const float*)d_in[5];
    const float* sbk = (const float*)d_in[6];
    const float* sbv = (const float*)d_in[7];
    const float* swo = (const float*)d_in[8];
    const float* sbo = (const float*)d_in[9];
    float* out = (float*)d_out;

    rsca_kernel<<<N_DIM, B_DIM>>>(x, y, swq, swk, swv, sbq, sbk, sbv, swo, sbo, out);
}